// round 5
// baseline (speedup 1.0000x reference)
#include <cuda_runtime.h>
#include <cuda_bf16.h>
#include <cuda_fp8.h>
#include <cstdint>
#include <math.h>

// ============================================================================
// Problem constants
// ============================================================================

static constexpr int D_IN  = 1024;
static constexpr int D_OUT = 1024;
static constexpr int M_MAX = 32768;

static constexpr int TILE_M = 128;
static constexpr int TILE_N = 128;
static constexpr int KCH    = 128;              // K bytes per pipeline chunk
static constexpr int NCH    = D_IN / KCH;       // 8 chunks
static constexpr int STAGES = 3;
static constexpr int GEMM_THREADS = 256;        // 8 warps: 2 (M) x 4 (N)

static constexpr int STAGE_BYTES = (TILE_M + TILE_N) * KCH;   // 32 KB
static constexpr int SMEM_ALLOC  = STAGES * STAGE_BYTES;      // 96 KB

#define SWZ(off) ((off) ^ (((off) >> 3) & 0x70))

// ============================================================================
// Scratch (device globals: allocation-free)
// ============================================================================

__device__ __align__(16) unsigned char g_qx[(size_t)M_MAX * D_IN];
__device__ __align__(16) float g_xscale[M_MAX];
__device__ __align__(16) unsigned char g_qw[(size_t)D_OUT * D_IN];
__device__ int g_wmode;   // 0 = f32, 1 = bf16, 2 = raw fp8 bytes

// ============================================================================
// PTX wrappers (base compute_103-safe)
// ============================================================================

__device__ __forceinline__ uint32_t smem_to_u32(const void* smem_ptr) {
    uint32_t addr;
    asm("{ .reg .u64 tmp; cvta.to.shared.u64 tmp, %1; cvt.u32.u64 %0, tmp; }"
        : "=r"(addr) : "l"(smem_ptr));
    return addr;
}

__device__ __forceinline__ void cp_async16(uint32_t dst, const void* src) {
    asm volatile("cp.async.cg.shared.global [%0], [%1], 16;"
                 :: "r"(dst), "l"(src) : "memory");
}

#define CP_COMMIT() asm volatile("cp.async.commit_group;" ::: "memory")

__device__ __forceinline__ void ldmatrix_x4(uint32_t* r, uint32_t addr) {
    asm volatile("ldmatrix.sync.aligned.m8n8.x4.shared.b16 {%0,%1,%2,%3}, [%4];"
                 : "=r"(r[0]), "=r"(r[1]), "=r"(r[2]), "=r"(r[3])
                 : "r"(addr));
}

__device__ __forceinline__ void mma_fp8(
    float d[4], const uint32_t a[4], const uint32_t b0, const uint32_t b1)
{
    asm volatile(
        "mma.sync.aligned.m16n8k32.row.col.f32.e4m3.e4m3.f32 "
        "{%0,%1,%2,%3}, {%4,%5,%6,%7}, {%8,%9}, {%0,%1,%2,%3};"
        : "+f"(d[0]), "+f"(d[1]), "+f"(d[2]), "+f"(d[3])
        : "r"(a[0]), "r"(a[1]), "r"(a[2]), "r"(a[3]),
          "r"(b0), "r"(b1));
}

// ============================================================================
// Kernel 0a: detect how the harness serialized the fp8 weight.
// ============================================================================

__global__ void fp8ld_detect_kernel(const void* __restrict__ w)
{
    __shared__ int cf, cb;
    if (threadIdx.x == 0) { cf = 0; cb = 0; }
    __syncthreads();

    const float* wf = (const float*)w;
    const __nv_bfloat16* wb = (const __nv_bfloat16*)w;
    int okf = 0, okb = 0;
    for (int i = threadIdx.x; i < 2048; i += 256) {
        float v = wf[i];
        if (isfinite(v) && fabsf(v) <= 448.0f) okf++;
    }
    for (int i = threadIdx.x; i < 4096; i += 256) {
        float u = __bfloat162float(wb[i]);
        if (isfinite(u) && fabsf(u) <= 448.0f) okb++;
    }
    atomicAdd(&cf, okf);
    atomicAdd(&cb, okb);
    __syncthreads();
    if (threadIdx.x == 0) {
        if      (cf >= 1946) g_wmode = 0;
        else if (cb >= 3891) g_wmode = 1;
        else                 g_wmode = 2;
    }
}

// ============================================================================
// Kernel 0b: materialize canonical e4m3 weight bytes into g_qw.
// ============================================================================

__global__ void __launch_bounds__(256) fp8ld_prepw_kernel(const void* __restrict__ w)
{
    int mode = g_wmode;
    int i = blockIdx.x * 256 + threadIdx.x;           // quad index
    if (i >= (D_OUT * D_IN) / 4) return;

    uchar4 q;
    if (mode == 0) {
        float4 v = ((const float4*)w)[i];
        __nv_fp8x2_storage_t lo = __nv_cvt_float2_to_fp8x2(
            make_float2(v.x, v.y), __NV_SATFINITE, __NV_E4M3);
        __nv_fp8x2_storage_t hi = __nv_cvt_float2_to_fp8x2(
            make_float2(v.z, v.w), __NV_SATFINITE, __NV_E4M3);
        q.x = (unsigned char)(lo & 0xFF);
        q.y = (unsigned char)(lo >> 8);
        q.z = (unsigned char)(hi & 0xFF);
        q.w = (unsigned char)(hi >> 8);
    } else if (mode == 1) {
        const __nv_bfloat162* wb = (const __nv_bfloat162*)w;
        __nv_bfloat162 p0 = wb[i * 2];
        __nv_bfloat162 p1 = wb[i * 2 + 1];
        __nv_fp8x2_storage_t lo = __nv_cvt_float2_to_fp8x2(
            make_float2(__bfloat162float(p0.x), __bfloat162float(p0.y)),
            __NV_SATFINITE, __NV_E4M3);
        __nv_fp8x2_storage_t hi = __nv_cvt_float2_to_fp8x2(
            make_float2(__bfloat162float(p1.x), __bfloat162float(p1.y)),
            __NV_SATFINITE, __NV_E4M3);
        q.x = (unsigned char)(lo & 0xFF);
        q.y = (unsigned char)(lo >> 8);
        q.z = (unsigned char)(hi & 0xFF);
        q.w = (unsigned char)(hi >> 8);
    } else {
        q = ((const uchar4*)w)[i];
    }
    ((uchar4*)g_qw)[i] = q;
}

// ============================================================================
// Kernel 1: per-token dynamic fp8 quantization (1 warp / token)
// ============================================================================

__global__ void __launch_bounds__(256) fp8ld_quant_kernel(
    const float* __restrict__ x, int M)
{
    int token = blockIdx.x * 8 + (threadIdx.x >> 5);
    int lane  = threadIdx.x & 31;
    if (token >= M) return;

    const float4* xp = reinterpret_cast<const float4*>(x + (size_t)token * D_IN);
    float4 v[8];
    float amax = 0.0f;
#pragma unroll
    for (int i = 0; i < 8; i++) {
        v[i] = xp[lane + 32 * i];
        amax = fmaxf(amax, fmaxf(fmaxf(fabsf(v[i].x), fabsf(v[i].y)),
                                 fmaxf(fabsf(v[i].z), fabsf(v[i].w))));
    }
#pragma unroll
    for (int off = 16; off > 0; off >>= 1)
        amax = fmaxf(amax, __shfl_xor_sync(0xFFFFFFFFu, amax, off));

    float amax_c = fmaxf(amax, 1e-12f);
    float scale  = amax_c / 448.0f;
    float inv    = 448.0f / amax_c;

    if (lane == 0) g_xscale[token] = scale;

    uint32_t* qp = reinterpret_cast<uint32_t*>(g_qx + (size_t)token * D_IN);
#pragma unroll
    for (int i = 0; i < 8; i++) {
        float4 w = v[i];
        __nv_fp8x2_storage_t lo = __nv_cvt_float2_to_fp8x2(
            make_float2(w.x * inv, w.y * inv), __NV_SATFINITE, __NV_E4M3);
        __nv_fp8x2_storage_t hi = __nv_cvt_float2_to_fp8x2(
            make_float2(w.z * inv, w.w * inv), __NV_SATFINITE, __NV_E4M3);
        qp[lane + 32 * i] = (uint32_t)lo | ((uint32_t)hi << 16);
    }
}

// ============================================================================
// Kernel 2: fp8 GEMM via mma.sync.m16n8k32 + fused dequant/bias epilogue
//   2 CTAs/SM; register-double-buffered ldmatrix pipeline.
// ============================================================================

__device__ __forceinline__ void issue_chunk(
    uint32_t sb, int m0, int n0, int kc, int tid)
{
    int s = kc % STAGES;
    uint32_t a_base = sb + s * STAGE_BYTES;
    uint32_t b_base = a_base + TILE_M * KCH;
    size_t koff = (size_t)kc * KCH;
#pragma unroll
    for (int j = 0; j < 4; j++) {
        int c   = tid + j * GEMM_THREADS;   // 0..1023 16B-chunk index
        int row = c >> 3;
        int kk  = (c & 7) << 4;
        uint32_t sw = SWZ((uint32_t)(row * KCH + kk));
        cp_async16(a_base + sw, g_qx + (size_t)(m0 + row) * D_IN + koff + kk);
        cp_async16(b_base + sw, g_qw + (size_t)(n0 + row) * D_IN + koff + kk);
    }
    CP_COMMIT();
}

__global__ void __launch_bounds__(GEMM_THREADS, 2) fp8ld_gemm_kernel(
    const float* __restrict__ wscale_p,
    const float* __restrict__ bias,
    float* __restrict__ out,
    int M)
{
    extern __shared__ char smem[];
    uint32_t sb = smem_to_u32(smem);
    int tid = threadIdx.x;
    int wid = tid >> 5;
    int L   = tid & 31;
    int wm  = wid >> 2;       // 0..1  (M)
    int wn  = wid & 3;        // 0..3  (N)
    int n0  = blockIdx.x * TILE_N;
    int m0  = blockIdx.y * TILE_M;

    float d[4][4][4];
#pragma unroll
    for (int i = 0; i < 4; i++)
#pragma unroll
        for (int j = 0; j < 4; j++)
#pragma unroll
            for (int r = 0; r < 4; r++) d[i][j][r] = 0.0f;

    // Prologue: 2 chunks in flight
    issue_chunk(sb, m0, n0, 0, tid);
    issue_chunk(sb, m0, n0, 1, tid);

    // Per-lane ldmatrix in-stage offsets (stage base added per chunk).
    uint32_t a_off = SWZ((uint32_t)(
        (wm * 64 + ((L >> 3) & 1) * 8 + (L & 7)) * KCH + (L >> 4) * 16));
    uint32_t b_off = SWZ((uint32_t)(
        (wn * 32 + (L >> 4) * 8 + (L & 7)) * KCH + ((L >> 3) & 1) * 16));

#pragma unroll 1
    for (int kc = 0; kc < NCH; kc++) {
        if (kc == NCH - 1) asm volatile("cp.async.wait_group 0;" ::: "memory");
        else               asm volatile("cp.async.wait_group 1;" ::: "memory");
        __syncthreads();
        if (kc + 2 < NCH) issue_chunk(sb, m0, n0, kc + 2, tid);

        int s = kc % STAGES;
        uint32_t a_base = sb + s * STAGE_BYTES + a_off;
        uint32_t b_base = sb + s * STAGE_BYTES + (uint32_t)(TILE_M * KCH) + b_off;

        // SWZ(x + ks*32) == SWZ(x) ^ (ks*32) for offsets within a 128B row
        // (no carries into the swizzle source bits).
#define A_ADDR(ks, i) ((a_base + (uint32_t)((i) * 16 * KCH)) ^ (uint32_t)((ks) * 32))
#define B_ADDR(ks, h) ((b_base + (uint32_t)((h) * 16 * KCH)) ^ (uint32_t)((ks) * 32))

        // Register-double-buffered fragment pipeline:
        //   bf[buf][0..7]  : B fragments for one K=32 step (n0..31)
        //   af[buf][0..3]  : A fragments for one 16-row tile
        uint32_t bf[2][8];
        uint32_t af[2][4];

        ldmatrix_x4(&bf[0][0], B_ADDR(0, 0));
        ldmatrix_x4(&bf[0][4], B_ADDR(0, 1));
        ldmatrix_x4(af[0], A_ADDR(0, 0));

#pragma unroll
        for (int ks = 0; ks < 4; ks++) {             // 4 x K=32 per chunk
            int cur = ks & 1, nxt = cur ^ 1;
            if (ks < 3) {
                ldmatrix_x4(&bf[nxt][0], B_ADDR(ks + 1, 0));
                ldmatrix_x4(&bf[nxt][4], B_ADDR(ks + 1, 1));
            }
#pragma unroll
            for (int i = 0; i < 4; i++) {
                int ap = i & 1, an = ap ^ 1;
                if (i < 3)        ldmatrix_x4(af[an], A_ADDR(ks, i + 1));
                else if (ks < 3)  ldmatrix_x4(af[an], A_ADDR(ks + 1, 0));
                mma_fp8(d[i][0], af[ap], bf[cur][0], bf[cur][1]);
                mma_fp8(d[i][1], af[ap], bf[cur][2], bf[cur][3]);
                mma_fp8(d[i][2], af[ap], bf[cur][4], bf[cur][5]);
                mma_fp8(d[i][3], af[ap], bf[cur][6], bf[cur][7]);
            }
        }
#undef A_ADDR
#undef B_ADDR
    }

    // Epilogue: out = d * x_scale[m] * w_scale + bias[n]
    float wsc = *wscale_p;
    int ncol0 = n0 + wn * 32;
#pragma unroll
    for (int i = 0; i < 4; i++) {
        int mlo = m0 + wm * 64 + i * 16 + (L >> 2);
        float xs0 = g_xscale[mlo]     * wsc;
        float xs1 = g_xscale[mlo + 8] * wsc;
        float* r0 = out + (size_t)mlo * D_OUT + ncol0;
        float* r1 = r0 + (size_t)8 * D_OUT;
#pragma unroll
        for (int j = 0; j < 4; j++) {
            int c = j * 8 + (L & 3) * 2;
            float b0 = bias[ncol0 + c];
            float b1 = bias[ncol0 + c + 1];
            float2 lo = make_float2(d[i][j][0] * xs0 + b0, d[i][j][1] * xs0 + b1);
            float2 hi = make_float2(d[i][j][2] * xs1 + b0, d[i][j][3] * xs1 + b1);
            *reinterpret_cast<float2*>(r0 + c) = lo;
            *reinterpret_cast<float2*>(r1 + c) = hi;
        }
    }
}

// ============================================================================
// Launch
// ============================================================================

extern "C" void kernel_launch(void* const* d_in, const int* in_sizes, int n_in,
                              void* d_out, int out_size)
{
    const float* x      = (const float*)d_in[0];
    const void*  weight = (const void*)d_in[1];   // dtype probed at runtime
    const float* wscale = (const float*)d_in[2];
    const float* bias   = (const float*)d_in[3];
    float*       out    = (float*)d_out;

    int M = in_sizes[0] / D_IN;   // 32768

    fp8ld_detect_kernel<<<1, 256>>>(weight);
    fp8ld_prepw_kernel<<<(D_OUT * D_IN / 4 + 255) / 256, 256>>>(weight);
    fp8ld_quant_kernel<<<(M + 7) / 8, 256>>>(x, M);

    cudaFuncSetAttribute(fp8ld_gemm_kernel,
                         cudaFuncAttributeMaxDynamicSharedMemorySize, SMEM_ALLOC);
    dim3 grid(D_OUT / TILE_N, M / TILE_M);   // (8, 256)
    fp8ld_gemm_kernel<<<grid, GEMM_THREADS, SMEM_ALLOC>>>(wscale, bias, out, M);
}

// round 6
// speedup vs baseline: 1.0562x; 1.0562x over previous
#include <cuda_runtime.h>
#include <cuda_bf16.h>
#include <cuda_fp8.h>
#include <cstdint>
#include <math.h>

// ============================================================================
// Problem constants
// ============================================================================

static constexpr int D_IN  = 1024;
static constexpr int D_OUT = 1024;
static constexpr int M_MAX = 32768;

static constexpr int TILE_M = 128;
static constexpr int TILE_N = 128;
static constexpr int KCH    = 128;              // K bytes per pipeline chunk
static constexpr int NCH    = D_IN / KCH;       // 8 chunks
static constexpr int STAGES = 3;
static constexpr int GEMM_THREADS = 128;        // 4 warps: 2 (M) x 2 (N), 64x64 each

static constexpr int STAGE_BYTES = (TILE_M + TILE_N) * KCH;   // 32 KB
static constexpr int SMEM_ALLOC  = STAGES * STAGE_BYTES;      // 96 KB

#define SWZ(off) ((off) ^ (((off) >> 3) & 0x70))

// ============================================================================
// Scratch (device globals: allocation-free)
// ============================================================================

__device__ __align__(16) unsigned char g_qx[(size_t)M_MAX * D_IN];
__device__ __align__(16) float g_xscale[M_MAX];
__device__ __align__(16) unsigned char g_qw[(size_t)D_OUT * D_IN];
__device__ int g_wmode;   // 0 = f32, 1 = bf16, 2 = raw fp8 bytes

// ============================================================================
// PTX wrappers (base compute_103-safe)
// ============================================================================

__device__ __forceinline__ uint32_t smem_to_u32(const void* smem_ptr) {
    uint32_t addr;
    asm("{ .reg .u64 tmp; cvta.to.shared.u64 tmp, %1; cvt.u32.u64 %0, tmp; }"
        : "=r"(addr) : "l"(smem_ptr));
    return addr;
}

__device__ __forceinline__ void cp_async16(uint32_t dst, const void* src) {
    asm volatile("cp.async.cg.shared.global [%0], [%1], 16;"
                 :: "r"(dst), "l"(src) : "memory");
}

#define CP_COMMIT() asm volatile("cp.async.commit_group;" ::: "memory")

__device__ __forceinline__ void ldmatrix_x4(uint32_t* r, uint32_t addr) {
    asm volatile("ldmatrix.sync.aligned.m8n8.x4.shared.b16 {%0,%1,%2,%3}, [%4];"
                 : "=r"(r[0]), "=r"(r[1]), "=r"(r[2]), "=r"(r[3])
                 : "r"(addr));
}

__device__ __forceinline__ void mma_fp8(
    float d[4], const uint32_t a[4], const uint32_t b0, const uint32_t b1)
{
    asm volatile(
        "mma.sync.aligned.m16n8k32.row.col.f32.e4m3.e4m3.f32 "
        "{%0,%1,%2,%3}, {%4,%5,%6,%7}, {%8,%9}, {%0,%1,%2,%3};"
        : "+f"(d[0]), "+f"(d[1]), "+f"(d[2]), "+f"(d[3])
        : "r"(a[0]), "r"(a[1]), "r"(a[2]), "r"(a[3]),
          "r"(b0), "r"(b1));
}

// ============================================================================
// Kernel 0a: detect how the harness serialized the fp8 weight.
// ============================================================================

__global__ void fp8ld_detect_kernel(const void* __restrict__ w)
{
    __shared__ int cf, cb;
    if (threadIdx.x == 0) { cf = 0; cb = 0; }
    __syncthreads();

    const float* wf = (const float*)w;
    const __nv_bfloat16* wb = (const __nv_bfloat16*)w;
    int okf = 0, okb = 0;
    for (int i = threadIdx.x; i < 2048; i += 256) {
        float v = wf[i];
        if (isfinite(v) && fabsf(v) <= 448.0f) okf++;
    }
    for (int i = threadIdx.x; i < 4096; i += 256) {
        float u = __bfloat162float(wb[i]);
        if (isfinite(u) && fabsf(u) <= 448.0f) okb++;
    }
    atomicAdd(&cf, okf);
    atomicAdd(&cb, okb);
    __syncthreads();
    if (threadIdx.x == 0) {
        if      (cf >= 1946) g_wmode = 0;
        else if (cb >= 3891) g_wmode = 1;
        else                 g_wmode = 2;
    }
}

// ============================================================================
// Kernel 0b: materialize canonical e4m3 weight bytes into g_qw.
// ============================================================================

__global__ void __launch_bounds__(256) fp8ld_prepw_kernel(const void* __restrict__ w)
{
    int mode = g_wmode;
    int i = blockIdx.x * 256 + threadIdx.x;           // quad index
    if (i >= (D_OUT * D_IN) / 4) return;

    uchar4 q;
    if (mode == 0) {
        float4 v = ((const float4*)w)[i];
        __nv_fp8x2_storage_t lo = __nv_cvt_float2_to_fp8x2(
            make_float2(v.x, v.y), __NV_SATFINITE, __NV_E4M3);
        __nv_fp8x2_storage_t hi = __nv_cvt_float2_to_fp8x2(
            make_float2(v.z, v.w), __NV_SATFINITE, __NV_E4M3);
        q.x = (unsigned char)(lo & 0xFF);
        q.y = (unsigned char)(lo >> 8);
        q.z = (unsigned char)(hi & 0xFF);
        q.w = (unsigned char)(hi >> 8);
    } else if (mode == 1) {
        const __nv_bfloat162* wb = (const __nv_bfloat162*)w;
        __nv_bfloat162 p0 = wb[i * 2];
        __nv_bfloat162 p1 = wb[i * 2 + 1];
        __nv_fp8x2_storage_t lo = __nv_cvt_float2_to_fp8x2(
            make_float2(__bfloat162float(p0.x), __bfloat162float(p0.y)),
            __NV_SATFINITE, __NV_E4M3);
        __nv_fp8x2_storage_t hi = __nv_cvt_float2_to_fp8x2(
            make_float2(__bfloat162float(p1.x), __bfloat162float(p1.y)),
            __NV_SATFINITE, __NV_E4M3);
        q.x = (unsigned char)(lo & 0xFF);
        q.y = (unsigned char)(lo >> 8);
        q.z = (unsigned char)(hi & 0xFF);
        q.w = (unsigned char)(hi >> 8);
    } else {
        q = ((const uchar4*)w)[i];
    }
    ((uchar4*)g_qw)[i] = q;
}

// ============================================================================
// Kernel 1: per-token dynamic fp8 quantization (1 warp / token)
// ============================================================================

__global__ void __launch_bounds__(256) fp8ld_quant_kernel(
    const float* __restrict__ x, int M)
{
    int token = blockIdx.x * 8 + (threadIdx.x >> 5);
    int lane  = threadIdx.x & 31;
    if (token >= M) return;

    const float4* xp = reinterpret_cast<const float4*>(x + (size_t)token * D_IN);
    float4 v[8];
    float amax = 0.0f;
#pragma unroll
    for (int i = 0; i < 8; i++) {
        v[i] = xp[lane + 32 * i];
        amax = fmaxf(amax, fmaxf(fmaxf(fabsf(v[i].x), fabsf(v[i].y)),
                                 fmaxf(fabsf(v[i].z), fabsf(v[i].w))));
    }
#pragma unroll
    for (int off = 16; off > 0; off >>= 1)
        amax = fmaxf(amax, __shfl_xor_sync(0xFFFFFFFFu, amax, off));

    float amax_c = fmaxf(amax, 1e-12f);
    float scale  = amax_c / 448.0f;
    float inv    = 448.0f / amax_c;

    if (lane == 0) g_xscale[token] = scale;

    uint32_t* qp = reinterpret_cast<uint32_t*>(g_qx + (size_t)token * D_IN);
#pragma unroll
    for (int i = 0; i < 8; i++) {
        float4 w = v[i];
        __nv_fp8x2_storage_t lo = __nv_cvt_float2_to_fp8x2(
            make_float2(w.x * inv, w.y * inv), __NV_SATFINITE, __NV_E4M3);
        __nv_fp8x2_storage_t hi = __nv_cvt_float2_to_fp8x2(
            make_float2(w.z * inv, w.w * inv), __NV_SATFINITE, __NV_E4M3);
        qp[lane + 32 * i] = (uint32_t)lo | ((uint32_t)hi << 16);
    }
}

// ============================================================================
// Kernel 2: fp8 GEMM via mma.sync.m16n8k32 + fused dequant/bias epilogue
//   128 threads / CTA (4 warps, 64x64 warp tiles), 2 CTAs/SM.
// ============================================================================

__device__ __forceinline__ void issue_chunk(
    uint32_t sb, int m0, int n0, int kc, int tid)
{
    int s = kc % STAGES;
    uint32_t a_base = sb + s * STAGE_BYTES;
    uint32_t b_base = a_base + TILE_M * KCH;
    size_t koff = (size_t)kc * KCH;
#pragma unroll
    for (int j = 0; j < 8; j++) {
        int c   = tid + j * GEMM_THREADS;   // 0..1023 16B-chunk index
        int row = c >> 3;
        int kk  = (c & 7) << 4;
        uint32_t sw = SWZ((uint32_t)(row * KCH + kk));
        cp_async16(a_base + sw, g_qx + (size_t)(m0 + row) * D_IN + koff + kk);
        cp_async16(b_base + sw, g_qw + (size_t)(n0 + row) * D_IN + koff + kk);
    }
    CP_COMMIT();
}

__global__ void __launch_bounds__(GEMM_THREADS, 2) fp8ld_gemm_kernel(
    const float* __restrict__ wscale_p,
    const float* __restrict__ bias,
    float* __restrict__ out,
    int M)
{
    extern __shared__ char smem[];
    uint32_t sb = smem_to_u32(smem);
    int tid = threadIdx.x;
    int wid = tid >> 5;
    int L   = tid & 31;
    int wm  = wid >> 1;       // 0..1  (M): 64 rows
    int wn  = wid & 1;        // 0..1  (N): 64 cols
    int n0  = blockIdx.x * TILE_N;
    int m0  = blockIdx.y * TILE_M;

    float d[4][8][4];
#pragma unroll
    for (int i = 0; i < 4; i++)
#pragma unroll
        for (int j = 0; j < 8; j++)
#pragma unroll
            for (int r = 0; r < 4; r++) d[i][j][r] = 0.0f;

    // Prologue: 2 chunks in flight
    issue_chunk(sb, m0, n0, 0, tid);
    issue_chunk(sb, m0, n0, 1, tid);

    // Per-lane ldmatrix in-stage offsets (stage base added per chunk).
    // A x4 tiles: [r0-7,k0-15][r8-15,k0-15][r0-7,k16-31][r8-15,k16-31]
    uint32_t a_off = SWZ((uint32_t)(
        (wm * 64 + ((L >> 3) & 1) * 8 + (L & 7)) * KCH + (L >> 4) * 16));
    // B x4 tiles: [n0-7,k0-15][n0-7,k16-31][n8-15,k0-15][n8-15,k16-31]
    uint32_t b_off = SWZ((uint32_t)(
        (wn * 64 + (L >> 4) * 8 + (L & 7)) * KCH + ((L >> 3) & 1) * 16));

#pragma unroll 1
    for (int kc = 0; kc < NCH; kc++) {
        if (kc == NCH - 1) asm volatile("cp.async.wait_group 0;" ::: "memory");
        else               asm volatile("cp.async.wait_group 1;" ::: "memory");
        __syncthreads();
        if (kc + 2 < NCH) issue_chunk(sb, m0, n0, kc + 2, tid);

        int s = kc % STAGES;
        uint32_t a_base = sb + s * STAGE_BYTES + a_off;
        uint32_t b_base = sb + s * STAGE_BYTES + (uint32_t)(TILE_M * KCH) + b_off;

        // SWZ(x + ks*32) == SWZ(x) ^ (ks*32): ks*32 touches only bits [5:6],
        // which the swizzle passes through and XORs independently.
#pragma unroll
        for (int ks = 0; ks < 4; ks++) {             // 4 x K=32 per chunk
            uint32_t kx = (uint32_t)(ks * 32);
            uint32_t bfr[4][4];                       // 64 N-cols of B
#pragma unroll
            for (int t = 0; t < 4; t++)
                ldmatrix_x4(bfr[t], (b_base + (uint32_t)(t * 16 * KCH)) ^ kx);
#pragma unroll
            for (int i = 0; i < 4; i++) {             // 4 x 16 M-rows of A
                uint32_t a[4];
                ldmatrix_x4(a, (a_base + (uint32_t)(i * 16 * KCH)) ^ kx);
#pragma unroll
                for (int t = 0; t < 4; t++) {
                    mma_fp8(d[i][2 * t + 0], a, bfr[t][0], bfr[t][1]);
                    mma_fp8(d[i][2 * t + 1], a, bfr[t][2], bfr[t][3]);
                }
            }
        }
    }

    // Epilogue: out = d * x_scale[m] * w_scale + bias[n]
    float wsc = *wscale_p;
    int ncol0 = n0 + wn * 64;
#pragma unroll
    for (int i = 0; i < 4; i++) {
        int mlo = m0 + wm * 64 + i * 16 + (L >> 2);
        float xs0 = g_xscale[mlo]     * wsc;
        float xs1 = g_xscale[mlo + 8] * wsc;
        float* r0 = out + (size_t)mlo * D_OUT + ncol0;
        float* r1 = r0 + (size_t)8 * D_OUT;
#pragma unroll
        for (int j = 0; j < 8; j++) {
            int c = j * 8 + (L & 3) * 2;
            float b0 = bias[ncol0 + c];
            float b1 = bias[ncol0 + c + 1];
            float2 lo = make_float2(d[i][j][0] * xs0 + b0, d[i][j][1] * xs0 + b1);
            float2 hi = make_float2(d[i][j][2] * xs1 + b0, d[i][j][3] * xs1 + b1);
            *reinterpret_cast<float2*>(r0 + c) = lo;
            *reinterpret_cast<float2*>(r1 + c) = hi;
        }
    }
}

// ============================================================================
// Launch
// ============================================================================

extern "C" void kernel_launch(void* const* d_in, const int* in_sizes, int n_in,
                              void* d_out, int out_size)
{
    const float* x      = (const float*)d_in[0];
    const void*  weight = (const void*)d_in[1];   // dtype probed at runtime
    const float* wscale = (const float*)d_in[2];
    const float* bias   = (const float*)d_in[3];
    float*       out    = (float*)d_out;

    int M = in_sizes[0] / D_IN;   // 32768

    fp8ld_detect_kernel<<<1, 256>>>(weight);
    fp8ld_prepw_kernel<<<(D_OUT * D_IN / 4 + 255) / 256, 256>>>(weight);
    fp8ld_quant_kernel<<<(M + 7) / 8, 256>>>(x, M);

    cudaFuncSetAttribute(fp8ld_gemm_kernel,
                         cudaFuncAttributeMaxDynamicSharedMemorySize, SMEM_ALLOC);
    dim3 grid(D_OUT / TILE_N, M / TILE_M);   // (8, 256)
    fp8ld_gemm_kernel<<<grid, GEMM_THREADS, SMEM_ALLOC>>>(wscale, bias, out, M);
}